// round 4
// baseline (speedup 1.0000x reference)
#include <cuda_runtime.h>
#include <cstdint>

#define NN   8192
#define KF   256
#define KX   512
#define TOPC 32
#define EPSF 1e-10f

// ---------------- device scratch ----------------
__device__ float  g_X[(size_t)NN * KX];   // [n][0..255]=A_m*cos, [256..511]=A_m*sin
__device__ float  g_sq[NN];
__device__ float  g_d[NN];                // rowsum + eps (fp32, XLA-order)
__device__ double g_rowPS[NN];
__device__ int    g_rowPC[NN];
__device__ float  g_tau;

// =====================================================================
// Stage A: top-32 mask, features, sq. One warp per row.
// =====================================================================
__global__ void prep_kernel(const float* __restrict__ P, const float* __restrict__ A) {
    int warp = threadIdx.x >> 5, lane = threadIdx.x & 31;
    int n = blockIdx.x * 4 + warp;
    if (n >= NN) return;
    const float* Arow = A + (size_t)n * KF;
    const float* Prow = P + (size_t)n * KF;

    float a[8], tmp[8];
#pragma unroll
    for (int j = 0; j < 8; j++) { a[j] = Arow[j * 32 + lane]; tmp[j] = a[j]; }

    unsigned sel = 0u;
    for (int it = 0; it < TOPC; it++) {
        float lm = -1e30f; int jb = 0;
#pragma unroll
        for (int j = 0; j < 8; j++) if (tmp[j] > lm) { lm = tmp[j]; jb = j; }
        float M = lm;
#pragma unroll
        for (int o = 16; o; o >>= 1) M = fmaxf(M, __shfl_xor_sync(0xffffffffu, M, o));
        unsigned ball = __ballot_sync(0xffffffffu, lm == M);
        int src = __ffs(ball) - 1;
        if (lane == src) { tmp[jb] = -1e30f; sel |= 1u << jb; }
    }

    float sq = 0.f;
#pragma unroll
    for (int j = 0; j < 8; j++) {
        int k = j * 32 + lane;
        float am = (sel >> j & 1u) ? a[j] : 0.f;
        sq = __fmaf_rn(am, am, sq);
        float p = Prow[k];
        float cc = cosf(p);      // libdevice __nv_cosf (matches XLA:GPU)
        float ss = sinf(p);
        g_X[(size_t)n * KX + k]      = __fmul_rn(am, cc);
        g_X[(size_t)n * KX + KF + k] = __fmul_rn(am, ss);
    }
#pragma unroll
    for (int o = 16; o; o >>= 1) sq = __fadd_rn(sq, __shfl_xor_sync(0xffffffffu, sq, o));
    if (lane == 0) g_sq[n] = sq;
}

// =====================================================================
// Stage B: R tile GEMM, fp32 sequential-k FMA (replicates cublas/Eigen
// rounding). cos-part accumulator then sin-part accumulator, one add.
// 128x128 tiles, 256 threads, 8x8 micro-tile. Triangular + mirror.
// =====================================================================
#define TS 128
#define KT 16

__global__ void __launch_bounds__(256) sgemm_kernel(float* __restrict__ out) {
    int bi = blockIdx.y, bj = blockIdx.x;
    if (bj > bi) return;
    int bm = bi * TS, bn = bj * TS;
    int tid = threadIdx.x;
    int tx = tid & 15, ty = tid >> 4;

    __shared__ float sA[KT][TS + 4];   // [k][m]
    __shared__ float sB[KT][TS + 4];

    float4 pa[2], pb[2];

#define LDG_TILE(KTI)                                                          \
    {                                                                          \
        _Pragma("unroll")                                                      \
        for (int i = 0; i < 2; i++) {                                          \
            int f = tid + i * 256;                                             \
            int row = f >> 2, kq = f & 3;                                      \
            pa[i] = *(const float4*)&g_X[(size_t)(bm + row) * KX + (KTI) * KT + kq * 4]; \
            pb[i] = *(const float4*)&g_X[(size_t)(bn + row) * KX + (KTI) * KT + kq * 4]; \
        }                                                                      \
    }

#define STS_TILE()                                                             \
    {                                                                          \
        _Pragma("unroll")                                                      \
        for (int i = 0; i < 2; i++) {                                          \
            int f = tid + i * 256;                                             \
            int row = f >> 2, kq = f & 3;                                      \
            sA[kq * 4 + 0][row] = pa[i].x; sA[kq * 4 + 1][row] = pa[i].y;      \
            sA[kq * 4 + 2][row] = pa[i].z; sA[kq * 4 + 3][row] = pa[i].w;      \
            sB[kq * 4 + 0][row] = pb[i].x; sB[kq * 4 + 1][row] = pb[i].y;      \
            sB[kq * 4 + 2][row] = pb[i].z; sB[kq * 4 + 3][row] = pb[i].w;      \
        }                                                                      \
    }

#define COMPUTE_TILE(ACC)                                                      \
    {                                                                          \
        _Pragma("unroll")                                                      \
        for (int kk = 0; kk < KT; kk++) {                                      \
            float4 a0 = *(const float4*)&sA[kk][ty * 8];                       \
            float4 a1 = *(const float4*)&sA[kk][ty * 8 + 4];                   \
            float4 b0 = *(const float4*)&sB[kk][tx * 8];                       \
            float4 b1 = *(const float4*)&sB[kk][tx * 8 + 4];                   \
            float av[8] = {a0.x, a0.y, a0.z, a0.w, a1.x, a1.y, a1.z, a1.w};    \
            float bv[8] = {b0.x, b0.y, b0.z, b0.w, b1.x, b1.y, b1.z, b1.w};    \
            _Pragma("unroll")                                                  \
            for (int r = 0; r < 8; r++)                                        \
                _Pragma("unroll")                                              \
                for (int c = 0; c < 8; c++)                                    \
                    ACC[r][c] = __fmaf_rn(av[r], bv[c], ACC[r][c]);            \
        }                                                                      \
    }

    float accC[8][8], accS[8][8];
#pragma unroll
    for (int r = 0; r < 8; r++)
#pragma unroll
        for (int c = 0; c < 8; c++) { accC[r][c] = 0.f; accS[r][c] = 0.f; }

    LDG_TILE(0);
    for (int kt = 0; kt < 16; kt++) {          // cos features, k ascending
        __syncthreads();
        STS_TILE();
        __syncthreads();
        LDG_TILE(kt + 1);
        COMPUTE_TILE(accC);
    }
    for (int kt = 16; kt < 32; kt++) {         // sin features, k ascending
        __syncthreads();
        STS_TILE();
        __syncthreads();
        if (kt + 1 < 32) LDG_TILE(kt + 1);
        COMPUTE_TILE(accS);
    }

    // -------- epilogue: R = (accC+accS)/sqrt(sq_i*sq_j+eps), mirror --------
    float sqi[8], sqj[8];
#pragma unroll
    for (int r = 0; r < 8; r++) sqi[r] = g_sq[bm + ty * 8 + r];
#pragma unroll
    for (int c = 0; c < 8; c++) sqj[c] = g_sq[bn + tx * 8 + c];

    float v[8][8];
#pragma unroll
    for (int r = 0; r < 8; r++)
#pragma unroll
        for (int c = 0; c < 8; c++) {
            float num = __fadd_rn(accC[r][c], accS[r][c]);
            float den = __fsqrt_rn(__fadd_rn(__fmul_rn(sqi[r], sqj[c]), EPSF));
            v[r][c] = __fdiv_rn(num, den);
        }

#pragma unroll
    for (int r = 0; r < 8; r++) {
        size_t o = (size_t)(bm + ty * 8 + r) * NN + bn + tx * 8;
        *(float4*)&out[o]     = make_float4(v[r][0], v[r][1], v[r][2], v[r][3]);
        *(float4*)&out[o + 4] = make_float4(v[r][4], v[r][5], v[r][6], v[r][7]);
    }
    if (bi != bj) {
#pragma unroll
        for (int c = 0; c < 8; c++) {
            size_t o = (size_t)(bn + tx * 8 + c) * NN + bm + ty * 8;
            *(float4*)&out[o]     = make_float4(v[0][c], v[1][c], v[2][c], v[3][c]);
            *(float4*)&out[o + 4] = make_float4(v[4][c], v[5][c], v[6][c], v[7][c]);
        }
    }
}

// =====================================================================
// Stage C (fused): rowsum in fp32 (XLA:GPU reduction order) + positive
// stats of R' = R/d, computed from register-held values (no re-read).
// 1024 threads/row, x2 vectorized strided accumulation, shfl trees.
// =====================================================================
__global__ void __launch_bounds__(1024) rowsum_kernel(const float* __restrict__ R) {
    int row = blockIdx.x;
    const float* r = R + (size_t)row * NN;
    int t = threadIdx.x;

    float vals[8];
    float a0 = 0.f, a1 = 0.f;
#pragma unroll
    for (int j = 0; j < 4; j++) {
        int i = t * 2 + j * 2048;
        vals[j * 2]     = r[i];
        vals[j * 2 + 1] = r[i + 1];
        a0 = __fadd_rn(a0, vals[j * 2]);
        a1 = __fadd_rn(a1, vals[j * 2 + 1]);
    }
    float acc = __fadd_rn(a0, a1);
#pragma unroll
    for (int o = 16; o > 0; o >>= 1)
        acc = __fadd_rn(acc, __shfl_down_sync(0xffffffffu, acc, o));
    __shared__ float w[32];
    __shared__ float sd;
    if ((t & 31) == 0) w[t >> 5] = acc;
    __syncthreads();
    if (t < 32) {
        float vv = w[t];
#pragma unroll
        for (int o = 16; o > 0; o >>= 1)
            vv = __fadd_rn(vv, __shfl_down_sync(0xffffffffu, vv, o));
        if (t == 0) { float d = __fadd_rn(vv, EPSF); g_d[row] = d; sd = d; }
    }
    __syncthreads();

    // positive stats of R/d from registers
    float d = sd;
    double ps = 0.0; int pc = 0;
#pragma unroll
    for (int j = 0; j < 8; j++) {
        float rp = __fdiv_rn(vals[j], d);
        if (rp > 0.f) { ps += (double)rp; pc++; }
    }
#pragma unroll
    for (int o = 16; o > 0; o >>= 1) {
        ps += __shfl_down_sync(0xffffffffu, ps, o);
        pc += __shfl_down_sync(0xffffffffu, pc, o);
    }
    __shared__ double wps[32];
    __shared__ int    wpc[32];
    if ((t & 31) == 0) { wps[t >> 5] = ps; wpc[t >> 5] = pc; }
    __syncthreads();
    if (t < 32) {
        double p2 = wps[t]; int c2 = wpc[t];
#pragma unroll
        for (int o = 16; o > 0; o >>= 1) {
            p2 += __shfl_down_sync(0xffffffffu, p2, o);
            c2 += __shfl_down_sync(0xffffffffu, c2, o);
        }
        if (t == 0) { g_rowPS[row] = p2; g_rowPC[row] = c2; }
    }
}

// =====================================================================
// Stage D: tau = mean of strictly-positive R' (fp32 final ops like ref)
// =====================================================================
__global__ void __launch_bounds__(1024) tau_kernel() {
    __shared__ double sps[1024]; __shared__ long long spc[1024];
    double ps = 0.0; long long pc = 0;
    for (int rw = threadIdx.x; rw < NN; rw += 1024) { ps += g_rowPS[rw]; pc += g_rowPC[rw]; }
    sps[threadIdx.x] = ps; spc[threadIdx.x] = pc;
    __syncthreads();
    for (int o = 512; o > 0; o >>= 1) {
        if (threadIdx.x < o) {
            sps[threadIdx.x] += sps[threadIdx.x + o];
            spc[threadIdx.x] += spc[threadIdx.x + o];
        }
        __syncthreads();
    }
    if (threadIdx.x == 0) {
        float psf = (float)sps[0];
        float cf  = fmaxf((float)spc[0], 1.0f);   // int count -> f32 (like astype)
        float mean = __fdiv_rn(psf, cf);
        g_tau = (mean > 0.f) ? mean : 1.0f;       // TAU_FACTOR = 1.0
    }
}

// =====================================================================
// Stage E: R_hat = where(R/d >= tau, R/d, 0)   (in-place)
// =====================================================================
__global__ void thresh_kernel(float* __restrict__ out) {
    float tau = g_tau;
    const size_t tot = (size_t)NN * NN / 4;
    for (size_t i = (size_t)blockIdx.x * blockDim.x + threadIdx.x; i < tot;
         i += (size_t)gridDim.x * blockDim.x) {
        int row = (int)(i >> 11);
        float d = g_d[row];
        float4 v = ((const float4*)out)[i];
        v.x = __fdiv_rn(v.x, d); v.y = __fdiv_rn(v.y, d);
        v.z = __fdiv_rn(v.z, d); v.w = __fdiv_rn(v.w, d);
        v.x = (v.x >= tau) ? v.x : 0.f;
        v.y = (v.y >= tau) ? v.y : 0.f;
        v.z = (v.z >= tau) ? v.z : 0.f;
        v.w = (v.w >= tau) ? v.w : 0.f;
        ((float4*)out)[i] = v;
    }
}

// =====================================================================
extern "C" void kernel_launch(void* const* d_in, const int* in_sizes, int n_in,
                              void* d_out, int out_size) {
    const float* P = (const float*)d_in[0];
    const float* A = (const float*)d_in[1];
    float* out = (float*)d_out;

    prep_kernel<<<NN / 4, 128>>>(P, A);
    sgemm_kernel<<<dim3(64, 64), 256>>>(out);
    rowsum_kernel<<<NN, 1024>>>(out);
    tau_kernel<<<1, 1024>>>();
    thresh_kernel<<<4096, 256>>>(out);
}